// round 10
// baseline (speedup 1.0000x reference)
#include <cuda_runtime.h>
#include <math.h>
#include <stdint.h>

#define NPTS   262144
#define NPART  24
#define CC     24
#define RR     128
#define TILE   64
#define THREADS 256
#define AS     72      // activation smem stride: 72 % 32 == 8 -> B-operand conflict-free

// Channel-last triplanes: [p][k][y][x][c], 24*3*128*128*24 floats = 113 MB
__device__ float g_planes[(size_t)NPART * 3 * RR * RR * CC];
__device__ float g_bl_eff[128];
// Fragment-packed tf32 weights (prepass output): [mg][ks][lane][mt][4]
__device__ __align__(16) float g_W1p[4 * 9 * 256];    // 9216
__device__ __align__(16) float g_W2p[4 * 16 * 256];   // 16384
__device__ __align__(16) float g_Wfp[4 * 16 * 256];   // 16384
__device__ __align__(16) float g_Wlp[4 * 16 * 256];   // 16384 (cols 0-127; latent folded)
__device__ __align__(16) float g_Wvp[2 * 20 * 256];   // 10240 (K padded 155->160)

__device__ __forceinline__ float to_tf32(float x) {
    uint32_t y;
    asm("cvt.rna.tf32.f32 %0, %1;" : "=r"(y) : "f"(x));
    return __uint_as_float(y);
}

// ---------------------------------------------------------------------------
// Fragment packing: dst[(((mg*KS+ks)*32+lane)*2+mt)*4+e] = W[m][k] (tf32)
//   m = mg*32 + mt*16 + (lane>>2) + ((e&1)<<3)
//   k = ks*8 + (lane&3) + ((e>>1)<<2),  zero when k >= realK
// ---------------------------------------------------------------------------
__device__ __forceinline__ void pack_frag(float* dst, const float* __restrict__ src,
                                          int wstride, int realK,
                                          int MG, int KS, int g, int STR) {
    int total = MG * KS * 256;
    for (int i = g; i < total; i += STR) {
        int e    = i & 3;
        int mt   = (i >> 2) & 1;
        int lane = (i >> 3) & 31;
        int rest = i >> 8;
        int ks   = rest % KS;
        int mg   = rest / KS;
        int m = mg * 32 + mt * 16 + (lane >> 2) + ((e & 1) << 3);
        int k = ks * 8 + (lane & 3) + ((e >> 1) << 2);
        dst[i] = (k < realK) ? to_tf32(src[m * wstride + k]) : 0.f;
    }
}

// ---------------------------------------------------------------------------
// Prepass: blockIdx.y < 72 -> triplane transpose; blockIdx.y == 72 -> weight
// fragment packing + bl_eff (latent fold). One launch.
// ---------------------------------------------------------------------------
__global__ void prepass(const float* __restrict__ tp,
                        const float* __restrict__ W1, const float* __restrict__ W2,
                        const float* __restrict__ Wf, const float* __restrict__ Wl,
                        const float* __restrict__ Wv,
                        const float* __restrict__ bl,
                        const float* __restrict__ nf_latent,
                        const int* __restrict__ ind) {
    int t = threadIdx.x;
    if (blockIdx.y == NPART * 3) {
        int g = blockIdx.x * THREADS + t;
        const int STR = RR * THREADS;
        pack_frag(g_W1p, W1, 72,  72,  4, 9,  g, STR);
        pack_frag(g_W2p, W2, 128, 128, 4, 16, g, STR);
        pack_frag(g_Wfp, Wf, 128, 128, 4, 16, g, STR);
        pack_frag(g_Wlp, Wl, 256, 128, 4, 16, g, STR);
        pack_frag(g_Wvp, Wv, 155, 155, 2, 20, g, STR);
        if (blockIdx.x == 0 && t < 128) {
            const float* L = nf_latent + (size_t)ind[0] * 128;
            float s = bl[t];
            #pragma unroll 4
            for (int l = 0; l < 128; ++l) s += Wl[t * 256 + 128 + l] * L[l];
            g_bl_eff[t] = s;
        }
        return;
    }

    __shared__ float tile[CC][136];
    int y  = blockIdx.x;
    int pk = blockIdx.y;
    int p = pk / 3, k = pk % 3;
    for (int it = t; it < CC * RR; it += THREADS) {
        int c = it >> 7;
        int x = it & 127;
        tile[c][x] = tp[(((size_t)(p * 72 + k * 24 + c) * RR + y) * RR) + x];
    }
    __syncthreads();
    float* dst = g_planes + (((size_t)(p * 3 + k) * RR + y) * RR) * CC;
    for (int it = t; it < CC * RR; it += THREADS) {
        int x = it / 24;
        int c = it - x * 24;
        dst[it] = tile[c][x];
    }
}

// ---------------------------------------------------------------------------
// tf32 layer: actout[OUT][64] = act(W @ actin[KS*8][64] + bias)
// A-operand: fragment-packed LDG.128 from global (registers, no smem).
// B-operand: LDS from activation smem (stride AS=72, conflict-free).
// 8 warps, warp tile 32(M) x 32(N): OUT=128 -> 4x2 (all), OUT=64 -> 2x2 (4 warps).
// ---------------------------------------------------------------------------
template<int KS, int OUT, bool RELU, bool ROUND_OUT>
__device__ __forceinline__ void layer_mma(const float* __restrict__ gWp,
                                          const float* __restrict__ bias,
                                          const float* actin, float* actout, int t) {
    const int lane = t & 31;
    const int wid  = t >> 5;
    const int arow = lane >> 2;   // 0..7
    const int acol = lane & 3;    // 0..3
    constexpr int MG = OUT / 32;  // 4 (OUT=128) or 2 (OUT=64)
    const int mg = wid & (MG - 1);
    const int ng = wid / MG;      // 0..1 active (N = 64 = 2 x 32)

    if (ng < 2) {
        const int Mbase = mg * 32;
        const int Nbase = ng * 32;

        float c[2][4][4];
        #pragma unroll
        for (int mt = 0; mt < 2; ++mt)
            #pragma unroll
            for (int nt = 0; nt < 4; ++nt)
                #pragma unroll
                for (int u = 0; u < 4; ++u) c[mt][nt][u] = 0.f;

        const float4* ap = (const float4*)gWp + (size_t)(mg * KS) * 64 + lane * 2;

        #pragma unroll 4
        for (int ks = 0; ks < KS; ++ks) {
            float4 a0 = __ldg(ap);
            float4 a1 = __ldg(ap + 1);
            ap += 64;
            int k0 = ks * 8;
            uint32_t B[4][2];
            #pragma unroll
            for (int nt = 0; nt < 4; ++nt) {
                const float* ab = actin + (k0 + acol) * AS + Nbase + nt * 8 + arow;
                B[nt][0] = __float_as_uint(ab[0]);
                B[nt][1] = __float_as_uint(ab[4 * AS]);
            }
            uint32_t A0x = __float_as_uint(a0.x), A0y = __float_as_uint(a0.y);
            uint32_t A0z = __float_as_uint(a0.z), A0w = __float_as_uint(a0.w);
            uint32_t A1x = __float_as_uint(a1.x), A1y = __float_as_uint(a1.y);
            uint32_t A1z = __float_as_uint(a1.z), A1w = __float_as_uint(a1.w);
            #pragma unroll
            for (int nt = 0; nt < 4; ++nt) {
                asm volatile(
                    "mma.sync.aligned.m16n8k8.row.col.f32.tf32.tf32.f32 "
                    "{%0,%1,%2,%3}, {%4,%5,%6,%7}, {%8,%9}, {%0,%1,%2,%3};"
                    : "+f"(c[0][nt][0]), "+f"(c[0][nt][1]),
                      "+f"(c[0][nt][2]), "+f"(c[0][nt][3])
                    : "r"(A0x), "r"(A0y), "r"(A0z), "r"(A0w),
                      "r"(B[nt][0]), "r"(B[nt][1]));
            }
            #pragma unroll
            for (int nt = 0; nt < 4; ++nt) {
                asm volatile(
                    "mma.sync.aligned.m16n8k8.row.col.f32.tf32.tf32.f32 "
                    "{%0,%1,%2,%3}, {%4,%5,%6,%7}, {%8,%9}, {%0,%1,%2,%3};"
                    : "+f"(c[1][nt][0]), "+f"(c[1][nt][1]),
                      "+f"(c[1][nt][2]), "+f"(c[1][nt][3])
                    : "r"(A1x), "r"(A1y), "r"(A1z), "r"(A1w),
                      "r"(B[nt][0]), "r"(B[nt][1]));
            }
        }

        #pragma unroll
        for (int mt = 0; mt < 2; ++mt) {
            int m0 = Mbase + mt * 16 + arow;
            float bv0 = __ldg(bias + m0);
            float bv1 = __ldg(bias + m0 + 8);
            #pragma unroll
            for (int nt = 0; nt < 4; ++nt) {
                int n0 = Nbase + nt * 8 + 2 * acol;
                float r0 = c[mt][nt][0] + bv0, r1 = c[mt][nt][1] + bv0;
                float r2 = c[mt][nt][2] + bv1, r3 = c[mt][nt][3] + bv1;
                if (RELU) {
                    r0 = fmaxf(r0, 0.f); r1 = fmaxf(r1, 0.f);
                    r2 = fmaxf(r2, 0.f); r3 = fmaxf(r3, 0.f);
                }
                if (ROUND_OUT) {
                    r0 = to_tf32(r0); r1 = to_tf32(r1);
                    r2 = to_tf32(r2); r3 = to_tf32(r3);
                }
                *(float2*)(actout + m0 * AS + n0)       = make_float2(r0, r1);
                *(float2*)(actout + (m0 + 8) * AS + n0) = make_float2(r2, r3);
            }
        }
    }
    __syncthreads();
}

// ---------------------------------------------------------------------------
// Main fused kernel: one block = 64 points; 2 CTAs/SM for latency hiding.
// ---------------------------------------------------------------------------
__global__ void __launch_bounds__(THREADS, 2)
tpose_kernel(const float* __restrict__ part_coord,
             const float* __restrict__ viewdir,
             const float* __restrict__ part_bounds,
             const float* __restrict__ b1, const float* __restrict__ b2,
             const float* __restrict__ Wa, const float* __restrict__ ba,
             const float* __restrict__ bf,
             const float* __restrict__ bv,
             const float* __restrict__ Wr, const float* __restrict__ br,
             const int* __restrict__ part_idx,
             float* __restrict__ out) {
    extern __shared__ float smem[];
    float* bufA = smem;                    // 160 rows x AS = 11520
    float* bufB = bufA + 160 * AS;         // 128 rows x AS = 9216
    float* scratch = bufB + 128 * AS;      // 1152 words: sampling / alpha reduce
    int*   sO00 = (int*)scratch;
    int*   sO01 = sO00 + 3 * TILE;
    int*   sO10 = sO01 + 3 * TILE;
    int*   sO11 = sO10 + 3 * TILE;
    float* sWx  = (float*)(sO11 + 3 * TILE);
    float* sWy  = sWx + 3 * TILE;

    int t = threadIdx.x;
    int tile0 = blockIdx.x * TILE;

    // --- phase 0: sampling params (t<192) || view posenc (t>=192) ---
    if (t < 3 * TILE) {
        int pt = t & 63;
        int k  = t / TILE;                 // 0..2
        int n  = tile0 + pt;
        float P[3] = { part_coord[3*n], part_coord[3*n+1], part_coord[3*n+2] };
        int p = part_idx[n];
        // part_bounds layout (NPART,2,3): [mn_xyz, mx_xyz]
        const float* bb = part_bounds + p * 6;
        const int ka[3] = {0, 0, 1};
        const int kb[3] = {1, 2, 2};
        int da = ka[k], db = kb[k];
        float mnU = bb[da], mxU = bb[3 + da];
        float mnV = bb[db], mxV = bb[3 + db];
        float u = (P[da] - 0.5f * (mnU + mxU)) / (0.5f * (mxU - mnU));
        float v = (P[db] - 0.5f * (mnV + mxV)) / (0.5f * (mxV - mnV));
        float px = fminf(fmaxf((u + 1.f) * 0.5f * (RR - 1), 0.f), (float)(RR - 1));
        float py = fminf(fmaxf((v + 1.f) * 0.5f * (RR - 1), 0.f), (float)(RR - 1));
        float x0 = floorf(px), y0 = floorf(py);
        int x0i = (int)x0, y0i = (int)y0;
        int x1i = min(x0i + 1, RR - 1), y1i = min(y0i + 1, RR - 1);
        int rb = (p * 3 + k) * RR;
        sO00[t] = ((rb + y0i) * RR + x0i) * CC;
        sO01[t] = ((rb + y0i) * RR + x1i) * CC;
        sO10[t] = ((rb + y1i) * RR + x0i) * CC;
        sO11[t] = ((rb + y1i) * RR + x1i) * CC;
        sWx[t]  = px - x0;
        sWy[t]  = py - y0;
    } else {
        int pt = t - 3 * TILE;             // 0..63
        int n = tile0 + pt;
        float dd[3] = { viewdir[3*n], viewdir[3*n+1], viewdir[3*n+2] };
        bufA[128 * AS + pt] = to_tf32(dd[0]);
        bufA[129 * AS + pt] = to_tf32(dd[1]);
        bufA[130 * AS + pt] = to_tf32(dd[2]);
        #pragma unroll
        for (int f = 0; f < 4; ++f) {
            float fr = (float)(1 << f);
            #pragma unroll
            for (int dim = 0; dim < 3; ++dim) {
                float sv, cv;
                __sincosf(dd[dim] * fr, &sv, &cv);
                bufA[(131 + f * 6 + dim)     * AS + pt] = to_tf32(sv);
                bufA[(131 + f * 6 + 3 + dim) * AS + pt] = to_tf32(cv);
            }
        }
        #pragma unroll
        for (int r = 155; r < 160; ++r) bufA[r * AS + pt] = 0.f;
    }
    __syncthreads();

    // --- triplane gather: lanes 0..23 = channels (contiguous 96B reads) ---
    {
        int w = t >> 5, c = t & 31;        // 8 warps
        if (c < CC) {
            for (int idx = w; idx < 3 * TILE; idx += 8) {
                int o00 = sO00[idx], o01 = sO01[idx], o10 = sO10[idx], o11 = sO11[idx];
                float wx = sWx[idx], wy = sWy[idx];
                float f00 = g_planes[o00 + c], f01 = g_planes[o01 + c];
                float f10 = g_planes[o10 + c], f11 = g_planes[o11 + c];
                float f = f00 * (1.f - wx) * (1.f - wy) + f01 * wx * (1.f - wy)
                        + f10 * (1.f - wx) * wy        + f11 * wx * wy;
                int k = idx / TILE, pt = idx & 63;
                bufA[(k * CC + c) * AS + pt] = to_tf32(f);
            }
        }
    }
    __syncthreads();

    layer_mma<9,  128, true,  true >(g_W1p, b1,       bufA, bufB, t);  // net1
    layer_mma<16, 128, true,  true >(g_W2p, b2,       bufB, bufA, t);  // net2 -> bufA

    // alpha = Wa @ net2 + ba : 4-way split across 256 threads + smem reduce
    {
        int q = t >> 6, pt = t & 63;
        float s0 = 0.f, s1 = 0.f;
        int i0 = q * 32;
        #pragma unroll 8
        for (int i = 0; i < 32; i += 2) {
            s0 += __ldg(Wa + i0 + i)     * bufA[(i0 + i) * AS + pt];
            s1 += __ldg(Wa + i0 + i + 1) * bufA[(i0 + i + 1) * AS + pt];
        }
        scratch[q * TILE + pt] = s0 + s1;
    }
    __syncthreads();
    if (t < TILE) {
        out[tile0 + t] = scratch[t] + scratch[TILE + t]
                       + scratch[2 * TILE + t] + scratch[3 * TILE + t] + __ldg(ba);
    }

    layer_mma<16, 128, false, true >(g_Wfp, bf,       bufA, bufB, t);  // features1
    layer_mma<16, 128, false, true >(g_Wlp, g_bl_eff, bufB, bufA, t);  // features2 (latent folded)
    layer_mma<20, 64,  true,  false>(g_Wvp, bv,       bufA, bufB, t);  // h (fp32 out)

    // rgb = Wr @ h + br  -> out layout: [alpha(N)][r(N)][g(N)][b(N)]
    if (t < TILE) {
        float s0 = __ldg(br), s1 = __ldg(br + 1), s2 = __ldg(br + 2);
        #pragma unroll 4
        for (int i = 0; i < 64; ++i) {
            float h = bufB[i * AS + t];
            s0 += __ldg(Wr + i)       * h;
            s1 += __ldg(Wr + 64 + i)  * h;
            s2 += __ldg(Wr + 128 + i) * h;
        }
        int n = tile0 + t;
        out[NPTS + n]            = s0;
        out[NPTS + NPTS + n]     = s1;
        out[NPTS + 2 * NPTS + n] = s2;
    }
}

// ---------------------------------------------------------------------------
extern "C" void kernel_launch(void* const* d_in, const int* in_sizes, int n_in,
                              void* d_out, int out_size) {
    const float* part_coord     = (const float*)d_in[0];
    const float* viewdir        = (const float*)d_in[1];
    const float* part_bounds    = (const float*)d_in[2];
    const float* part_triplanes = (const float*)d_in[3];
    const float* nf_latent      = (const float*)d_in[4];
    const float* W1 = (const float*)d_in[5];  const float* b1 = (const float*)d_in[6];
    const float* W2 = (const float*)d_in[7];  const float* b2 = (const float*)d_in[8];
    const float* Wa = (const float*)d_in[9];  const float* ba = (const float*)d_in[10];
    const float* Wf = (const float*)d_in[11]; const float* bf = (const float*)d_in[12];
    const float* Wl = (const float*)d_in[13]; const float* bl = (const float*)d_in[14];
    const float* Wv = (const float*)d_in[15]; const float* bv = (const float*)d_in[16];
    const float* Wr = (const float*)d_in[17]; const float* br = (const float*)d_in[18];
    const int* part_idx = (const int*)d_in[19];
    const int* ind      = (const int*)d_in[20];
    float* out = (float*)d_out;

    prepass<<<dim3(RR, NPART * 3 + 1), THREADS>>>(part_triplanes,
                                                  W1, W2, Wf, Wl, Wv,
                                                  bl, nf_latent, ind);

    // bufA 160*72 + bufB 128*72 + scratch 1152 = 21888 words = 87552 B (2 CTAs/SM)
    const size_t SMEM = (size_t)(160 * AS + 128 * AS + 1152) * 4;
    (void)cudaFuncSetAttribute(tpose_kernel,
                               cudaFuncAttributeMaxDynamicSharedMemorySize, (int)SMEM);
    tpose_kernel<<<NPTS / TILE, THREADS, SMEM>>>(
        part_coord, viewdir, part_bounds,
        b1, b2, Wa, ba, bf, bv, Wr, br,
        part_idx, out);
}

// round 11
// speedup vs baseline: 1.2427x; 1.2427x over previous
#include <cuda_runtime.h>
#include <math.h>
#include <stdint.h>

#define NPTS   262144
#define NPART  24
#define CC     24
#define RR     128
#define TILE   64
#define THREADS 256
#define AS     72      // activation smem stride: 72 % 32 == 8 -> B-operand conflict-free

// Channel-last triplanes: [p][k][y][x][c], 24*3*128*128*24 floats = 113 MB
__device__ float g_planes[(size_t)NPART * 3 * RR * RR * CC];
__device__ float g_bl_eff[128];
// Fragment-packed tf32 weights (prepass output): [mg][ks][lane][mt][4]
__device__ __align__(16) float g_W1p[4 * 9 * 256];    // 9216
__device__ __align__(16) float g_W2p[4 * 16 * 256];   // 16384
__device__ __align__(16) float g_Wfp[4 * 16 * 256];   // 16384
__device__ __align__(16) float g_Wlp[4 * 16 * 256];   // 16384 (cols 0-127; latent folded)
__device__ __align__(16) float g_Wvp[2 * 20 * 256];   // 10240 (K padded 155->160)

__device__ __forceinline__ float to_tf32(float x) {
    uint32_t y;
    asm("cvt.rna.tf32.f32 %0, %1;" : "=r"(y) : "f"(x));
    return __uint_as_float(y);
}

// ---------------------------------------------------------------------------
// Fragment packing: dst[(((mg*KS+ks)*32+lane)*2+mt)*4+e] = W[m][k] (tf32)
//   m = mg*32 + mt*16 + (lane>>2) + ((e&1)<<3)
//   k = ks*8 + (lane&3) + ((e>>1)<<2),  zero when k >= realK
// ---------------------------------------------------------------------------
__device__ __forceinline__ void pack_frag(float* dst, const float* __restrict__ src,
                                          int wstride, int realK,
                                          int MG, int KS, int g, int STR) {
    int total = MG * KS * 256;
    for (int i = g; i < total; i += STR) {
        int e    = i & 3;
        int mt   = (i >> 2) & 1;
        int lane = (i >> 3) & 31;
        int rest = i >> 8;
        int ks   = rest % KS;
        int mg   = rest / KS;
        int m = mg * 32 + mt * 16 + (lane >> 2) + ((e & 1) << 3);
        int k = ks * 8 + (lane & 3) + ((e >> 1) << 2);
        dst[i] = (k < realK) ? to_tf32(src[m * wstride + k]) : 0.f;
    }
}

// ---------------------------------------------------------------------------
// Prepass: blockIdx.y < 72 -> triplane transpose (float4 both gmem sides);
// blockIdx.y == 72 -> weight fragment packing + bl_eff. One launch.
// ---------------------------------------------------------------------------
__global__ void prepass(const float* __restrict__ tp,
                        const float* __restrict__ W1, const float* __restrict__ W2,
                        const float* __restrict__ Wf, const float* __restrict__ Wl,
                        const float* __restrict__ Wv,
                        const float* __restrict__ bl,
                        const float* __restrict__ nf_latent,
                        const int* __restrict__ ind) {
    int t = threadIdx.x;
    if (blockIdx.y == NPART * 3) {
        int g = blockIdx.x * THREADS + t;
        const int STR = RR * THREADS;
        pack_frag(g_W1p, W1, 72,  72,  4, 9,  g, STR);
        pack_frag(g_W2p, W2, 128, 128, 4, 16, g, STR);
        pack_frag(g_Wfp, Wf, 128, 128, 4, 16, g, STR);
        pack_frag(g_Wlp, Wl, 256, 128, 4, 16, g, STR);
        pack_frag(g_Wvp, Wv, 155, 155, 2, 20, g, STR);
        if (blockIdx.x == 0 && t < 128) {
            const float* L = nf_latent + (size_t)ind[0] * 128;
            float s = bl[t];
            #pragma unroll 4
            for (int l = 0; l < 128; ++l) s += Wl[t * 256 + 128 + l] * L[l];
            g_bl_eff[t] = s;
        }
        return;
    }

    __shared__ float tile[CC][129];
    int y  = blockIdx.x;
    int pk = blockIdx.y;
    int p = pk / 3, k = pk % 3;
    // load: 24 rows x 32 float4 (coalesced LDG.128)
    for (int i = t; i < CC * (RR / 4); i += THREADS) {
        int c = i >> 5, x4 = i & 31;
        const float4 v = *(const float4*)(tp +
            (((size_t)(p * 72 + k * 24 + c) * RR + y) * RR) + x4 * 4);
        tile[c][x4 * 4 + 0] = v.x;
        tile[c][x4 * 4 + 1] = v.y;
        tile[c][x4 * 4 + 2] = v.z;
        tile[c][x4 * 4 + 3] = v.w;
    }
    __syncthreads();
    // store: 768 float4 contiguous (coalesced STG.128)
    float4* dst4 = (float4*)(g_planes + (((size_t)(p * 3 + k) * RR + y) * RR) * CC);
    for (int i = t; i < (CC * RR) / 4; i += THREADS) {
        int e = i * 4;
        float4 o;
        o.x = tile[(e    ) % 24][(e    ) / 24];
        o.y = tile[(e + 1) % 24][(e + 1) / 24];
        o.z = tile[(e + 2) % 24][(e + 2) / 24];
        o.w = tile[(e + 3) % 24][(e + 3) / 24];
        dst4[i] = o;
    }
}

// ---------------------------------------------------------------------------
// tf32 layer: actout[OUT][64] = act(W @ [act1 (KS1*8 rows); act2 (KS2*8 rows)] + bias)
// A-operand: fragment-packed LDG.128 from global. B: LDS (stride AS, conflict-free).
// 8 warps, warp tile 32(M) x 32(N). act2 may be null (KS2=0).
// ---------------------------------------------------------------------------
template<int KS1, int KS2, int OUT, bool RELU, bool ROUND_OUT>
__device__ __forceinline__ void layer_mma(const float* __restrict__ gWp,
                                          const float* __restrict__ bias,
                                          const float* act1, const float* act2,
                                          float* actout, int t) {
    const int lane = t & 31;
    const int wid  = t >> 5;
    const int arow = lane >> 2;   // 0..7
    const int acol = lane & 3;    // 0..3
    constexpr int MG = OUT / 32;  // 4 (OUT=128) or 2 (OUT=64)
    constexpr int KS = KS1 + KS2;
    const int mg = wid & (MG - 1);
    const int ng = wid / MG;

    if (ng < 2) {
        const int Mbase = mg * 32;
        const int Nbase = ng * 32;

        float c[2][4][4];
        #pragma unroll
        for (int mt = 0; mt < 2; ++mt)
            #pragma unroll
            for (int nt = 0; nt < 4; ++nt)
                #pragma unroll
                for (int u = 0; u < 4; ++u) c[mt][nt][u] = 0.f;

        const float4* ap = (const float4*)gWp + (size_t)(mg * KS) * 64 + lane * 2;

        #pragma unroll 4
        for (int ks = 0; ks < KS; ++ks) {
            float4 a0 = __ldg(ap);
            float4 a1 = __ldg(ap + 1);
            ap += 64;
            const float* actin = (KS2 == 0 || ks < KS1) ? act1 : act2;
            int k0 = (KS2 == 0 || ks < KS1) ? ks * 8 : (ks - KS1) * 8;
            uint32_t B[4][2];
            #pragma unroll
            for (int nt = 0; nt < 4; ++nt) {
                const float* ab = actin + (k0 + acol) * AS + Nbase + nt * 8 + arow;
                B[nt][0] = __float_as_uint(ab[0]);
                B[nt][1] = __float_as_uint(ab[4 * AS]);
            }
            uint32_t A0x = __float_as_uint(a0.x), A0y = __float_as_uint(a0.y);
            uint32_t A0z = __float_as_uint(a0.z), A0w = __float_as_uint(a0.w);
            uint32_t A1x = __float_as_uint(a1.x), A1y = __float_as_uint(a1.y);
            uint32_t A1z = __float_as_uint(a1.z), A1w = __float_as_uint(a1.w);
            #pragma unroll
            for (int nt = 0; nt < 4; ++nt) {
                asm volatile(
                    "mma.sync.aligned.m16n8k8.row.col.f32.tf32.tf32.f32 "
                    "{%0,%1,%2,%3}, {%4,%5,%6,%7}, {%8,%9}, {%0,%1,%2,%3};"
                    : "+f"(c[0][nt][0]), "+f"(c[0][nt][1]),
                      "+f"(c[0][nt][2]), "+f"(c[0][nt][3])
                    : "r"(A0x), "r"(A0y), "r"(A0z), "r"(A0w),
                      "r"(B[nt][0]), "r"(B[nt][1]));
            }
            #pragma unroll
            for (int nt = 0; nt < 4; ++nt) {
                asm volatile(
                    "mma.sync.aligned.m16n8k8.row.col.f32.tf32.tf32.f32 "
                    "{%0,%1,%2,%3}, {%4,%5,%6,%7}, {%8,%9}, {%0,%1,%2,%3};"
                    : "+f"(c[1][nt][0]), "+f"(c[1][nt][1]),
                      "+f"(c[1][nt][2]), "+f"(c[1][nt][3])
                    : "r"(A1x), "r"(A1y), "r"(A1z), "r"(A1w),
                      "r"(B[nt][0]), "r"(B[nt][1]));
            }
        }

        #pragma unroll
        for (int mt = 0; mt < 2; ++mt) {
            int m0 = Mbase + mt * 16 + arow;
            float bv0 = __ldg(bias + m0);
            float bv1 = __ldg(bias + m0 + 8);
            #pragma unroll
            for (int nt = 0; nt < 4; ++nt) {
                int n0 = Nbase + nt * 8 + 2 * acol;
                float r0 = c[mt][nt][0] + bv0, r1 = c[mt][nt][1] + bv0;
                float r2 = c[mt][nt][2] + bv1, r3 = c[mt][nt][3] + bv1;
                if (RELU) {
                    r0 = fmaxf(r0, 0.f); r1 = fmaxf(r1, 0.f);
                    r2 = fmaxf(r2, 0.f); r3 = fmaxf(r3, 0.f);
                }
                if (ROUND_OUT) {
                    r0 = to_tf32(r0); r1 = to_tf32(r1);
                    r2 = to_tf32(r2); r3 = to_tf32(r3);
                }
                *(float2*)(actout + m0 * AS + n0)       = make_float2(r0, r1);
                *(float2*)(actout + (m0 + 8) * AS + n0) = make_float2(r2, r3);
            }
        }
    }
    __syncthreads();
}

// ---------------------------------------------------------------------------
// Main fused kernel: one block = 64 points; 3 CTAs/SM (72 KB smem).
// ---------------------------------------------------------------------------
__global__ void __launch_bounds__(THREADS, 3)
tpose_kernel(const float* __restrict__ part_coord,
             const float* __restrict__ viewdir,
             const float* __restrict__ part_bounds,
             const float* __restrict__ b1, const float* __restrict__ b2,
             const float* __restrict__ Wa, const float* __restrict__ ba,
             const float* __restrict__ bf,
             const float* __restrict__ bv,
             const float* __restrict__ Wr, const float* __restrict__ br,
             const int* __restrict__ part_idx,
             float* __restrict__ out) {
    extern __shared__ float smem[];
    float* bufA = smem;                    // 128 rows x AS
    float* bufB = bufA + 128 * AS;         // 128 rows x AS
    // sampling scratch overlaid on bufB (dead until layer1 epilogue)
    int*   sO00 = (int*)bufB;
    int*   sO01 = sO00 + 3 * TILE;
    int*   sO10 = sO01 + 3 * TILE;
    int*   sO11 = sO10 + 3 * TILE;
    float* sWx  = (float*)(sO11 + 3 * TILE);
    float* sWy  = sWx + 3 * TILE;
    float* aScr = bufB;                    // alpha reduce scratch (bufB dead then)

    int t = threadIdx.x;
    int tile0 = blockIdx.x * TILE;

    // --- phase 0: sampling params (one thread per (plane k, point)) ---
    if (t < 3 * TILE) {
        int pt = t & 63;
        int k  = t >> 6;                   // 0..2
        int n  = tile0 + pt;
        float P[3] = { part_coord[3*n], part_coord[3*n+1], part_coord[3*n+2] };
        int p = part_idx[n];
        // part_bounds layout (NPART,2,3): [mn_xyz, mx_xyz]
        const float* bb = part_bounds + p * 6;
        const int ka[3] = {0, 0, 1};
        const int kb[3] = {1, 2, 2};
        int da = ka[k], db = kb[k];
        float mnU = bb[da], mxU = bb[3 + da];
        float mnV = bb[db], mxV = bb[3 + db];
        float u = (P[da] - 0.5f * (mnU + mxU)) / (0.5f * (mxU - mnU));
        float v = (P[db] - 0.5f * (mnV + mxV)) / (0.5f * (mxV - mnV));
        float px = fminf(fmaxf((u + 1.f) * 0.5f * (RR - 1), 0.f), (float)(RR - 1));
        float py = fminf(fmaxf((v + 1.f) * 0.5f * (RR - 1), 0.f), (float)(RR - 1));
        float x0 = floorf(px), y0 = floorf(py);
        int x0i = (int)x0, y0i = (int)y0;
        int x1i = min(x0i + 1, RR - 1), y1i = min(y0i + 1, RR - 1);
        int rb = (p * 3 + k) * RR;
        sO00[t] = ((rb + y0i) * RR + x0i) * CC;
        sO01[t] = ((rb + y0i) * RR + x1i) * CC;
        sO10[t] = ((rb + y1i) * RR + x0i) * CC;
        sO11[t] = ((rb + y1i) * RR + x1i) * CC;
        sWx[t]  = px - x0;
        sWy[t]  = py - y0;
    }
    __syncthreads();

    // --- triplane gather: lanes 0..23 = channels (contiguous 96B reads) ---
    {
        int w = t >> 5, c = t & 31;        // 8 warps
        if (c < CC) {
            for (int idx = w; idx < 3 * TILE; idx += 8) {
                int o00 = sO00[idx], o01 = sO01[idx], o10 = sO10[idx], o11 = sO11[idx];
                float wx = sWx[idx], wy = sWy[idx];
                float f00 = g_planes[o00 + c], f01 = g_planes[o01 + c];
                float f10 = g_planes[o10 + c], f11 = g_planes[o11 + c];
                float f = f00 * (1.f - wx) * (1.f - wy) + f01 * wx * (1.f - wy)
                        + f10 * (1.f - wx) * wy        + f11 * wx * wy;
                int k = idx >> 6, pt = idx & 63;
                bufA[(k * CC + c) * AS + pt] = to_tf32(f);
            }
        }
    }
    __syncthreads();   // gather done (scratch in bufB dead after this)

    layer_mma<9,  0, 128, true,  true >(g_W1p, b1,       bufA, 0, bufB, t);  // net1
    layer_mma<16, 0, 128, true,  true >(g_W2p, b2,       bufB, 0, bufA, t);  // net2 -> bufA

    // alpha = Wa @ net2 + ba : 4-way split + smem reduce (scratch in dead bufB)
    {
        int q = t >> 6, pt = t & 63;
        float s0 = 0.f, s1 = 0.f;
        int i0 = q * 32;
        #pragma unroll 8
        for (int i = 0; i < 32; i += 2) {
            s0 += __ldg(Wa + i0 + i)     * bufA[(i0 + i) * AS + pt];
            s1 += __ldg(Wa + i0 + i + 1) * bufA[(i0 + i + 1) * AS + pt];
        }
        aScr[q * TILE + pt] = s0 + s1;
    }
    __syncthreads();
    if (t < TILE) {
        out[tile0 + t] = aScr[t] + aScr[TILE + t]
                       + aScr[2 * TILE + t] + aScr[3 * TILE + t] + __ldg(ba);
    }
    __syncthreads();   // protect aScr reads from features1 epilogue writes to bufB

    layer_mma<16, 0, 128, false, true >(g_Wfp, bf,       bufA, 0, bufB, t);  // features1
    layer_mma<16, 0, 128, false, true >(g_Wlp, g_bl_eff, bufB, 0, bufA, t);  // features2 (latent folded)

    // view posenc -> bufB rows 64..90 (27 rows), zero rows 91..95 (K pad to 160)
    // (bufB is dead after features2; last layer reads it as K-chunk 2)
    if (t < TILE) {
        int n = tile0 + t;
        float dd[3] = { viewdir[3*n], viewdir[3*n+1], viewdir[3*n+2] };
        float* vb = bufB + 64 * AS;
        vb[0 * AS + t] = to_tf32(dd[0]);
        vb[1 * AS + t] = to_tf32(dd[1]);
        vb[2 * AS + t] = to_tf32(dd[2]);
        #pragma unroll
        for (int f = 0; f < 4; ++f) {
            float fr = (float)(1 << f);
            #pragma unroll
            for (int dim = 0; dim < 3; ++dim) {
                float sv, cv;
                __sincosf(dd[dim] * fr, &sv, &cv);
                vb[(3 + f * 6 + dim)     * AS + t] = to_tf32(sv);
                vb[(3 + f * 6 + 3 + dim) * AS + t] = to_tf32(cv);
            }
        }
        #pragma unroll
        for (int r = 27; r < 32; ++r) vb[r * AS + t] = 0.f;
    }
    __syncthreads();

    // h = relu(Wv @ [features2 (128); vemb (32 padded)] + bv) -> bufB rows 0..63
    layer_mma<16, 4, 64, true, false>(g_Wvp, bv, bufA, bufB + 64 * AS, bufB, t);

    // rgb = Wr @ h + br  -> out layout: [alpha(N)][r(N)][g(N)][b(N)]
    if (t < TILE) {
        float s0 = __ldg(br), s1 = __ldg(br + 1), s2 = __ldg(br + 2);
        #pragma unroll 4
        for (int i = 0; i < 64; ++i) {
            float h = bufB[i * AS + t];
            s0 += __ldg(Wr + i)       * h;
            s1 += __ldg(Wr + 64 + i)  * h;
            s2 += __ldg(Wr + 128 + i) * h;
        }
        int n = tile0 + t;
        out[NPTS + n]            = s0;
        out[NPTS + NPTS + n]     = s1;
        out[NPTS + 2 * NPTS + n] = s2;
    }
}

// ---------------------------------------------------------------------------
extern "C" void kernel_launch(void* const* d_in, const int* in_sizes, int n_in,
                              void* d_out, int out_size) {
    const float* part_coord     = (const float*)d_in[0];
    const float* viewdir        = (const float*)d_in[1];
    const float* part_bounds    = (const float*)d_in[2];
    const float* part_triplanes = (const float*)d_in[3];
    const float* nf_latent      = (const float*)d_in[4];
    const float* W1 = (const float*)d_in[5];  const float* b1 = (const float*)d_in[6];
    const float* W2 = (const float*)d_in[7];  const float* b2 = (const float*)d_in[8];
    const float* Wa = (const float*)d_in[9];  const float* ba = (const float*)d_in[10];
    const float* Wf = (const float*)d_in[11]; const float* bf = (const float*)d_in[12];
    const float* Wl = (const float*)d_in[13]; const float* bl = (const float*)d_in[14];
    const float* Wv = (const float*)d_in[15]; const float* bv = (const float*)d_in[16];
    const float* Wr = (const float*)d_in[17]; const float* br = (const float*)d_in[18];
    const int* part_idx = (const int*)d_in[19];
    const int* ind      = (const int*)d_in[20];
    float* out = (float*)d_out;

    prepass<<<dim3(RR, NPART * 3 + 1), THREADS>>>(part_triplanes,
                                                  W1, W2, Wf, Wl, Wv,
                                                  bl, nf_latent, ind);

    // bufA 128*72 + bufB 128*72 = 18432 words = 73728 B -> 3 CTAs/SM
    const size_t SMEM = (size_t)(256 * AS) * 4;
    (void)cudaFuncSetAttribute(tpose_kernel,
                               cudaFuncAttributeMaxDynamicSharedMemorySize, (int)SMEM);
    tpose_kernel<<<NPTS / TILE, THREADS, SMEM>>>(
        part_coord, viewdir, part_bounds,
        b1, b2, Wa, ba, bf, bv, Wr, br,
        part_idx, out);
}

// round 12
// speedup vs baseline: 1.3073x; 1.0520x over previous
#include <cuda_runtime.h>
#include <math.h>
#include <stdint.h>

#define NPTS   262144
#define NPART  24
#define CC     24
#define RR     128
#define TILE   64
#define THREADS 256
#define AS     72      // activation smem stride: 72 % 32 == 8 -> B-operand conflict-free

// Channel-last triplanes: [p][k][y][x][c], 24*3*128*128*24 floats = 113 MB
__device__ float g_planes[(size_t)NPART * 3 * RR * RR * CC];
__device__ float g_bl_eff[128];
// Fragment-packed tf32 weights (prepass output): [mg][ks][lane][mt][4]
__device__ __align__(16) float g_W1p[4 * 9 * 256];    // 9216
__device__ __align__(16) float g_W2p[4 * 16 * 256];   // 16384
__device__ __align__(16) float g_Wfp[4 * 16 * 256];   // 16384
__device__ __align__(16) float g_Wlp[4 * 16 * 256];   // 16384 (cols 0-127; latent folded)
__device__ __align__(16) float g_Wvp[2 * 20 * 256];   // 10240 (K padded 155->160)

__device__ __forceinline__ float to_tf32(float x) {
    uint32_t y;
    asm("cvt.rna.tf32.f32 %0, %1;" : "=r"(y) : "f"(x));
    return __uint_as_float(y);
}

// ---------------------------------------------------------------------------
// Fragment packing: dst[(((mg*KS+ks)*32+lane)*2+mt)*4+e] = W[m][k] (tf32)
// ---------------------------------------------------------------------------
__device__ __forceinline__ void pack_frag(float* dst, const float* __restrict__ src,
                                          int wstride, int realK,
                                          int MG, int KS, int g, int STR) {
    int total = MG * KS * 256;
    for (int i = g; i < total; i += STR) {
        int e    = i & 3;
        int mt   = (i >> 2) & 1;
        int lane = (i >> 3) & 31;
        int rest = i >> 8;
        int ks   = rest % KS;
        int mg   = rest / KS;
        int m = mg * 32 + mt * 16 + (lane >> 2) + ((e & 1) << 3);
        int k = ks * 8 + (lane & 3) + ((e >> 1) << 2);
        dst[i] = (k < realK) ? to_tf32(src[m * wstride + k]) : 0.f;
    }
}

// ---------------------------------------------------------------------------
// Prepass: blockIdx.y < 72 -> triplane transpose (float4 both gmem sides);
// blockIdx.y == 72 -> weight fragment packing + bl_eff. One launch.
// ---------------------------------------------------------------------------
__global__ void prepass(const float* __restrict__ tp,
                        const float* __restrict__ W1, const float* __restrict__ W2,
                        const float* __restrict__ Wf, const float* __restrict__ Wl,
                        const float* __restrict__ Wv,
                        const float* __restrict__ bl,
                        const float* __restrict__ nf_latent,
                        const int* __restrict__ ind) {
    int t = threadIdx.x;
    if (blockIdx.y == NPART * 3) {
        int g = blockIdx.x * THREADS + t;
        const int STR = RR * THREADS;
        pack_frag(g_W1p, W1, 72,  72,  4, 9,  g, STR);
        pack_frag(g_W2p, W2, 128, 128, 4, 16, g, STR);
        pack_frag(g_Wfp, Wf, 128, 128, 4, 16, g, STR);
        pack_frag(g_Wlp, Wl, 256, 128, 4, 16, g, STR);
        pack_frag(g_Wvp, Wv, 155, 155, 2, 20, g, STR);
        if (blockIdx.x == 0 && t < 128) {
            const float* L = nf_latent + (size_t)ind[0] * 128;
            float s = bl[t];
            #pragma unroll 4
            for (int l = 0; l < 128; ++l) s += Wl[t * 256 + 128 + l] * L[l];
            g_bl_eff[t] = s;
        }
        return;
    }

    __shared__ float tile[CC][129];
    int y  = blockIdx.x;
    int pk = blockIdx.y;
    int p = pk / 3, k = pk % 3;
    for (int i = t; i < CC * (RR / 4); i += THREADS) {
        int c = i >> 5, x4 = i & 31;
        const float4 v = *(const float4*)(tp +
            (((size_t)(p * 72 + k * 24 + c) * RR + y) * RR) + x4 * 4);
        tile[c][x4 * 4 + 0] = v.x;
        tile[c][x4 * 4 + 1] = v.y;
        tile[c][x4 * 4 + 2] = v.z;
        tile[c][x4 * 4 + 3] = v.w;
    }
    __syncthreads();
    float4* dst4 = (float4*)(g_planes + (((size_t)(p * 3 + k) * RR + y) * RR) * CC);
    for (int i = t; i < (CC * RR) / 4; i += THREADS) {
        int e = i * 4;
        float4 o;
        o.x = tile[(e    ) % 24][(e    ) / 24];
        o.y = tile[(e + 1) % 24][(e + 1) / 24];
        o.z = tile[(e + 2) % 24][(e + 2) / 24];
        o.w = tile[(e + 3) % 24][(e + 3) / 24];
        dst4[i] = o;
    }
}

// ---------------------------------------------------------------------------
// tf32 layer, IN-PLACE capable: reads all inputs, block-syncs, writes outputs.
// actout may alias act1. A: fragment-packed LDG.128; B: conflict-free LDS.
// 8 warps, warp tile 32x32. act2 = second K source (vemb) or null (KS2=0).
// ---------------------------------------------------------------------------
template<int KS1, int KS2, int OUT, bool RELU, bool ROUND_OUT>
__device__ __forceinline__ void layer_mma(const float* __restrict__ gWp,
                                          const float* __restrict__ bias,
                                          const float* act1, const float* act2,
                                          float* actout, int t) {
    const int lane = t & 31;
    const int wid  = t >> 5;
    const int arow = lane >> 2;   // 0..7
    const int acol = lane & 3;    // 0..3
    constexpr int MG = OUT / 32;  // 4 (OUT=128) or 2 (OUT=64)
    constexpr int KS = KS1 + KS2;
    const int mg = wid & (MG - 1);
    const int ng = wid / MG;
    const bool active = (ng < 2);

    float c[2][4][4];
    #pragma unroll
    for (int mt = 0; mt < 2; ++mt)
        #pragma unroll
        for (int nt = 0; nt < 4; ++nt)
            #pragma unroll
            for (int u = 0; u < 4; ++u) c[mt][nt][u] = 0.f;

    const int Mbase = mg * 32;
    const int Nbase = ng * 32;

    if (active) {
        const float4* ap = (const float4*)gWp + (size_t)(mg * KS) * 64 + lane * 2;

        #pragma unroll 4
        for (int ks = 0; ks < KS; ++ks) {
            float4 a0 = __ldg(ap);
            float4 a1 = __ldg(ap + 1);
            ap += 64;
            const float* actin = (KS2 == 0 || ks < KS1) ? act1 : act2;
            int k0 = (KS2 == 0 || ks < KS1) ? ks * 8 : (ks - KS1) * 8;
            uint32_t B[4][2];
            #pragma unroll
            for (int nt = 0; nt < 4; ++nt) {
                const float* ab = actin + (k0 + acol) * AS + Nbase + nt * 8 + arow;
                B[nt][0] = __float_as_uint(ab[0]);
                B[nt][1] = __float_as_uint(ab[4 * AS]);
            }
            uint32_t A0x = __float_as_uint(a0.x), A0y = __float_as_uint(a0.y);
            uint32_t A0z = __float_as_uint(a0.z), A0w = __float_as_uint(a0.w);
            uint32_t A1x = __float_as_uint(a1.x), A1y = __float_as_uint(a1.y);
            uint32_t A1z = __float_as_uint(a1.z), A1w = __float_as_uint(a1.w);
            #pragma unroll
            for (int nt = 0; nt < 4; ++nt) {
                asm volatile(
                    "mma.sync.aligned.m16n8k8.row.col.f32.tf32.tf32.f32 "
                    "{%0,%1,%2,%3}, {%4,%5,%6,%7}, {%8,%9}, {%0,%1,%2,%3};"
                    : "+f"(c[0][nt][0]), "+f"(c[0][nt][1]),
                      "+f"(c[0][nt][2]), "+f"(c[0][nt][3])
                    : "r"(A0x), "r"(A0y), "r"(A0z), "r"(A0w),
                      "r"(B[nt][0]), "r"(B[nt][1]));
            }
            #pragma unroll
            for (int nt = 0; nt < 4; ++nt) {
                asm volatile(
                    "mma.sync.aligned.m16n8k8.row.col.f32.tf32.tf32.f32 "
                    "{%0,%1,%2,%3}, {%4,%5,%6,%7}, {%8,%9}, {%0,%1,%2,%3};"
                    : "+f"(c[1][nt][0]), "+f"(c[1][nt][1]),
                      "+f"(c[1][nt][2]), "+f"(c[1][nt][3])
                    : "r"(A1x), "r"(A1y), "r"(A1z), "r"(A1w),
                      "r"(B[nt][0]), "r"(B[nt][1]));
            }
        }
    }
    __syncthreads();   // all reads done before anyone writes (in-place safety)

    if (active) {
        #pragma unroll
        for (int mt = 0; mt < 2; ++mt) {
            int m0 = Mbase + mt * 16 + arow;
            float bv0 = __ldg(bias + m0);
            float bv1 = __ldg(bias + m0 + 8);
            #pragma unroll
            for (int nt = 0; nt < 4; ++nt) {
                int n0 = Nbase + nt * 8 + 2 * acol;
                float r0 = c[mt][nt][0] + bv0, r1 = c[mt][nt][1] + bv0;
                float r2 = c[mt][nt][2] + bv1, r3 = c[mt][nt][3] + bv1;
                if (RELU) {
                    r0 = fmaxf(r0, 0.f); r1 = fmaxf(r1, 0.f);
                    r2 = fmaxf(r2, 0.f); r3 = fmaxf(r3, 0.f);
                }
                if (ROUND_OUT) {
                    r0 = to_tf32(r0); r1 = to_tf32(r1);
                    r2 = to_tf32(r2); r3 = to_tf32(r3);
                }
                *(float2*)(actout + m0 * AS + n0)       = make_float2(r0, r1);
                *(float2*)(actout + (m0 + 8) * AS + n0) = make_float2(r2, r3);
            }
        }
    }
    __syncthreads();
}

// ---------------------------------------------------------------------------
// Main fused kernel: one block = 64 points; single in-place activation buffer
// -> 51.7 KB smem -> 4 CTAs/SM.
// ---------------------------------------------------------------------------
__global__ void __launch_bounds__(THREADS, 4)
tpose_kernel(const float* __restrict__ part_coord,
             const float* __restrict__ viewdir,
             const float* __restrict__ part_bounds,
             const float* __restrict__ b1, const float* __restrict__ b2,
             const float* __restrict__ Wa, const float* __restrict__ ba,
             const float* __restrict__ bf,
             const float* __restrict__ bv,
             const float* __restrict__ Wr, const float* __restrict__ br,
             const int* __restrict__ part_idx,
             float* __restrict__ out) {
    extern __shared__ float smem[];
    float* X    = smem;                    // 128 rows x AS = 9216 words (in-place)
    float* vemb = X + 128 * AS;            // 32 rows x AS = 2304 words
    float* scr  = vemb + 32 * AS;          // 1152 words: sampling scratch
    float* aScr = scr + 1152;              // 256 words: alpha reduce
    int*   sO00 = (int*)scr;
    int*   sO01 = sO00 + 3 * TILE;
    int*   sO10 = sO01 + 3 * TILE;
    int*   sO11 = sO10 + 3 * TILE;
    float* sWx  = (float*)(sO11 + 3 * TILE);
    float* sWy  = sWx + 3 * TILE;

    int t = threadIdx.x;
    int tile0 = blockIdx.x * TILE;

    // --- phase 0: sampling params (t<192) || view posenc (t>=192) ---
    if (t < 3 * TILE) {
        int pt = t & 63;
        int k  = t >> 6;                   // 0..2
        int n  = tile0 + pt;
        float P[3] = { part_coord[3*n], part_coord[3*n+1], part_coord[3*n+2] };
        int p = part_idx[n];
        // part_bounds layout (NPART,2,3): [mn_xyz, mx_xyz]
        const float* bb = part_bounds + p * 6;
        const int ka[3] = {0, 0, 1};
        const int kb[3] = {1, 2, 2};
        int da = ka[k], db = kb[k];
        float mnU = bb[da], mxU = bb[3 + da];
        float mnV = bb[db], mxV = bb[3 + db];
        float u = (P[da] - 0.5f * (mnU + mxU)) / (0.5f * (mxU - mnU));
        float v = (P[db] - 0.5f * (mnV + mxV)) / (0.5f * (mxV - mnV));
        float px = fminf(fmaxf((u + 1.f) * 0.5f * (RR - 1), 0.f), (float)(RR - 1));
        float py = fminf(fmaxf((v + 1.f) * 0.5f * (RR - 1), 0.f), (float)(RR - 1));
        float x0 = floorf(px), y0 = floorf(py);
        int x0i = (int)x0, y0i = (int)y0;
        int x1i = min(x0i + 1, RR - 1), y1i = min(y0i + 1, RR - 1);
        int rb = (p * 3 + k) * RR;
        sO00[t] = ((rb + y0i) * RR + x0i) * CC;
        sO01[t] = ((rb + y0i) * RR + x1i) * CC;
        sO10[t] = ((rb + y1i) * RR + x0i) * CC;
        sO11[t] = ((rb + y1i) * RR + x1i) * CC;
        sWx[t]  = px - x0;
        sWy[t]  = py - y0;
    } else {
        int pt = t - 3 * TILE;             // 0..63
        int n = tile0 + pt;
        float dd[3] = { viewdir[3*n], viewdir[3*n+1], viewdir[3*n+2] };
        vemb[0 * AS + pt] = to_tf32(dd[0]);
        vemb[1 * AS + pt] = to_tf32(dd[1]);
        vemb[2 * AS + pt] = to_tf32(dd[2]);
        #pragma unroll
        for (int f = 0; f < 4; ++f) {
            float fr = (float)(1 << f);
            #pragma unroll
            for (int dim = 0; dim < 3; ++dim) {
                float sv, cv;
                __sincosf(dd[dim] * fr, &sv, &cv);
                vemb[(3 + f * 6 + dim)     * AS + pt] = to_tf32(sv);
                vemb[(3 + f * 6 + 3 + dim) * AS + pt] = to_tf32(cv);
            }
        }
        #pragma unroll
        for (int r = 27; r < 32; ++r) vemb[r * AS + pt] = 0.f;
    }
    __syncthreads();

    // --- triplane gather: lanes 0..23 = channels (contiguous 96B reads) ---
    {
        int w = t >> 5, c = t & 31;        // 8 warps
        if (c < CC) {
            for (int idx = w; idx < 3 * TILE; idx += 8) {
                int o00 = sO00[idx], o01 = sO01[idx], o10 = sO10[idx], o11 = sO11[idx];
                float wx = sWx[idx], wy = sWy[idx];
                float f00 = g_planes[o00 + c], f01 = g_planes[o01 + c];
                float f10 = g_planes[o10 + c], f11 = g_planes[o11 + c];
                float f = f00 * (1.f - wx) * (1.f - wy) + f01 * wx * (1.f - wy)
                        + f10 * (1.f - wx) * wy        + f11 * wx * wy;
                int k = idx >> 6, pt = idx & 63;
                X[(k * CC + c) * AS + pt] = to_tf32(f);
            }
        }
    }
    __syncthreads();

    layer_mma<9,  0, 128, true,  true >(g_W1p, b1,       X, 0, X, t);  // net1
    layer_mma<16, 0, 128, true,  true >(g_W2p, b2,       X, 0, X, t);  // net2

    // alpha = Wa @ net2 + ba : 4-way split + smem reduce
    {
        int q = t >> 6, pt = t & 63;
        float s0 = 0.f, s1 = 0.f;
        int i0 = q * 32;
        #pragma unroll 8
        for (int i = 0; i < 32; i += 2) {
            s0 += __ldg(Wa + i0 + i)     * X[(i0 + i) * AS + pt];
            s1 += __ldg(Wa + i0 + i + 1) * X[(i0 + i + 1) * AS + pt];
        }
        aScr[q * TILE + pt] = s0 + s1;
    }
    __syncthreads();
    if (t < TILE) {
        out[tile0 + t] = aScr[t] + aScr[TILE + t]
                       + aScr[2 * TILE + t] + aScr[3 * TILE + t] + __ldg(ba);
    }

    layer_mma<16, 0, 128, false, true >(g_Wfp, bf,       X, 0, X, t);  // features1
    layer_mma<16, 0, 128, false, true >(g_Wlp, g_bl_eff, X, 0, X, t);  // features2

    // h = relu(Wv @ [features2 (128); vemb (32 padded)] + bv) -> X rows 0..63
    layer_mma<16, 4, 64, true, false>(g_Wvp, bv, X, vemb, X, t);

    // rgb = Wr @ h + br  -> out layout: [alpha(N)][r(N)][g(N)][b(N)]
    if (t < TILE) {
        float s0 = __ldg(br), s1 = __ldg(br + 1), s2 = __ldg(br + 2);
        #pragma unroll 4
        for (int i = 0; i < 64; ++i) {
            float h = X[i * AS + t];
            s0 += __ldg(Wr + i)       * h;
            s1 += __ldg(Wr + 64 + i)  * h;
            s2 += __ldg(Wr + 128 + i) * h;
        }
        int n = tile0 + t;
        out[NPTS + n]            = s0;
        out[NPTS + NPTS + n]     = s1;
        out[NPTS + 2 * NPTS + n] = s2;
    }
}

// ---------------------------------------------------------------------------
extern "C" void kernel_launch(void* const* d_in, const int* in_sizes, int n_in,
                              void* d_out, int out_size) {
    const float* part_coord     = (const float*)d_in[0];
    const float* viewdir        = (const float*)d_in[1];
    const float* part_bounds    = (const float*)d_in[2];
    const float* part_triplanes = (const float*)d_in[3];
    const float* nf_latent      = (const float*)d_in[4];
    const float* W1 = (const float*)d_in[5];  const float* b1 = (const float*)d_in[6];
    const float* W2 = (const float*)d_in[7];  const float* b2 = (const float*)d_in[8];
    const float* Wa = (const float*)d_in[9];  const float* ba = (const float*)d_in[10];
    const float* Wf = (const float*)d_in[11]; const float* bf = (const float*)d_in[12];
    const float* Wl = (const float*)d_in[13]; const float* bl = (const float*)d_in[14];
    const float* Wv = (const float*)d_in[15]; const float* bv = (const float*)d_in[16];
    const float* Wr = (const float*)d_in[17]; const float* br = (const float*)d_in[18];
    const int* part_idx = (const int*)d_in[19];
    const int* ind      = (const int*)d_in[20];
    float* out = (float*)d_out;

    prepass<<<dim3(RR, NPART * 3 + 1), THREADS>>>(part_triplanes,
                                                  W1, W2, Wf, Wl, Wv,
                                                  bl, nf_latent, ind);

    // X 9216 + vemb 2304 + scr 1152 + aScr 256 = 12928 words = 51712 B -> 4 CTAs/SM
    const size_t SMEM = (size_t)(128 * AS + 32 * AS + 1152 + 256) * 4;
    (void)cudaFuncSetAttribute(tpose_kernel,
                               cudaFuncAttributeMaxDynamicSharedMemorySize, (int)SMEM);
    tpose_kernel<<<NPTS / TILE, THREADS, SMEM>>>(
        part_coord, viewdir, part_bounds,
        b1, b2, Wa, ba, bf, bv, Wr, br,
        part_idx, out);
}